// round 9
// baseline (speedup 1.0000x reference)
#include <cuda_runtime.h>

#define NB 128   // persistent CTAs (1/SM, co-resident -> spin loops safe)
#define NT 256   // 8 warps
#define TT 2048
#define BB 8
#define HD 512
#define DI 256

// ---------------- device scratch (no cudaMalloc allowed) ----------------
// Tagged broadcast buffers: each element packs (uint tag << 32) | float_bits(h).
// Index: [buf][b*HD + j], buf in {0,1}.
__device__ unsigned long long g_hA[2 * BB * HD];   // h1 (layer0 out / layer1 in)
__device__ unsigned long long g_hB[2 * BB * HD];   // h2 (layer1 recurrent)

__global__ void init_kernel() {
    int i = blockIdx.x * blockDim.x + threadIdx.x;
    int stride = gridDim.x * blockDim.x;
    for (int k = i; k < 2 * BB * HD; k += stride) {
        g_hA[k] = 0ull;   // value 0.0f, tag 0
        g_hB[k] = 0ull;
    }
}

__device__ __forceinline__ float tanh_mufu(float x) {
    float y;
    asm("tanh.approx.f32 %0, %1;" : "=f"(y) : "f"(x));
    return y;
}
__device__ __forceinline__ float sigm(float x) {
    return fmaf(0.5f, tanh_mufu(0.5f * x), 0.5f);
}

// Packed dual-FMA on the sm_103a f32x2 pipe.
__device__ __forceinline__ void ffma2(unsigned long long& d, unsigned long long a,
                                      unsigned long long b) {
    asm("fma.rn.f32x2 %0, %1, %2, %0;" : "+l"(d) : "l"(a), "l"(b));
}

// 8B relaxed gpu-scope ops: single-word atomicity carries (h, tag) together.
__device__ __forceinline__ unsigned long long ld_tag(const unsigned long long* p) {
    unsigned long long v;
    asm volatile("ld.relaxed.gpu.global.b64 %0, [%1];" : "=l"(v) : "l"(p) : "memory");
    return v;
}
__device__ __forceinline__ void st_tag(unsigned long long* p, float h, unsigned tag) {
    unsigned long long v = ((unsigned long long)tag << 32) | (unsigned long long)__float_as_uint(h);
    asm volatile("st.relaxed.gpu.global.b64 [%0], %1;" :: "l"(p), "l"(v) : "memory");
}

// Register-weight dot: acc[g*8+b] += wgt[it][g] (lane's k-slice) * src[b].
template <int NIT, int STR>
__device__ __forceinline__ void dotr(unsigned long long* acc,
                                     const ulonglong2 (*wgt)[4],
                                     const float* __restrict__ src, int lane) {
#pragma unroll
    for (int it = 0; it < NIT; it++) {
        const float* s = src + it * 128 + lane * 4;
#pragma unroll
        for (int b = 0; b < 8; b++) {
            ulonglong2 v = *(const ulonglong2*)(s + b * STR);
#pragma unroll
            for (int g = 0; g < 4; g++) {
                ffma2(acc[g * 8 + b], wgt[it][g].x, v.x);
                ffma2(acc[g * 8 + b], wgt[it][g].y, v.y);
            }
        }
    }
}

// Horizontal f32x2 add + 31-shuffle reduce-scatter.
// Lane l ends owning the total for (gate = l>>3, batch = l&7).
__device__ __forceinline__ float hreduce(const unsigned long long* acc, int lane) {
    float av[32];
#pragma unroll
    for (int j = 0; j < 32; j++) {
        unsigned lo, hi;
        asm("mov.b64 {%0,%1}, %2;" : "=r"(lo), "=r"(hi) : "l"(acc[j]));
        av[j] = __uint_as_float(lo) + __uint_as_float(hi);
    }
#pragma unroll
    for (int m = 16; m > 0; m >>= 1) {
        const bool hi = (lane & m) != 0;
#pragma unroll
        for (int j = 0; j < m; j++) {
            float sendv = hi ? av[j] : av[j + m];
            float other = __shfl_xor_sync(0xffffffffu, sendv, m);
            av[j] = (hi ? av[j + m] : av[j]) + other;
        }
    }
    return av[0];
}

// Fused 2-layer wavefront: period p = layer0 step p + layer1 step p-1.
// Warp = (layer, column). All weights live in registers. Synchronization is
// purely data-driven via per-element tags (no flags, no fences, no grid bar).
__global__ void __launch_bounds__(NT, 1) lstm_fused_kernel(
    const float* __restrict__ x,
    const float* __restrict__ u0W, const float* __restrict__ w0W,
    const float* __restrict__ u0b, const float* __restrict__ w0b,
    const float* __restrict__ u1W, const float* __restrict__ w1W,
    const float* __restrict__ u1b, const float* __restrict__ w1b,
    float* __restrict__ h2seq, float* __restrict__ hh, float* __restrict__ cc)
{
    extern __shared__ float sm[];
    float* sA = sm;                  // 8*512  h1(p-1) stage
    float* sB = sA + BB * HD;        // 8*512  h2(p-2) stage
    float* sX = sB + BB * HD;        // 2 x 8*256  x double buffer

    const int tid  = threadIdx.x;
    const int bid  = blockIdx.x;
    const int w    = tid >> 5;
    const int lane = tid & 31;
    const bool L0  = (w < 4);
    const int jl   = L0 ? w : (w - 4);
    const int jg   = bid * 4 + jl;

    // ---- weights into registers (constant for all 2048 steps) ----
    ulonglong2 wA[4][4];   // recurrent U (K=512): [k-iter][gate]
    ulonglong2 wB[4][4];   // input W: L0 uses [0..1] (K=256), L1 [0..3] (K=512)
    {
        const float* Up = L0 ? u0W : u1W;
#pragma unroll
        for (int it = 0; it < 4; it++)
#pragma unroll
            for (int g = 0; g < 4; g++)
                wA[it][g] = *(const ulonglong2*)(Up + (size_t)(g * HD + jg) * HD
                                                 + it * 128 + lane * 4);
        if (L0) {
#pragma unroll
            for (int it = 0; it < 2; it++)
#pragma unroll
                for (int g = 0; g < 4; g++)
                    wB[it][g] = *(const ulonglong2*)(w0W + (size_t)(g * HD + jg) * DI
                                                     + it * 128 + lane * 4);
        } else {
#pragma unroll
            for (int it = 0; it < 4; it++)
#pragma unroll
                for (int g = 0; g < 4; g++)
                    wB[it][g] = *(const ulonglong2*)(w1W + (size_t)(g * HD + jg) * HD
                                                     + it * 128 + lane * 4);
        }
    }
    float bs0, bs1, bs2, bs3;
    {
        const float* ubp = L0 ? u0b : u1b;
        const float* wbp = L0 ? w0b : w1b;
        bs0 = ubp[0 * HD + jg] + wbp[0 * HD + jg];
        bs1 = ubp[1 * HD + jg] + wbp[1 * HD + jg];
        bs2 = ubp[2 * HD + jg] + wbp[2 * HD + jg];
        bs3 = ubp[3 * HD + jg] + wbp[3 * HD + jg];
    }
    float creg = 0.0f;   // cell state (column jg, batch=lane) on lanes 0-7

    // ---- stage x(0) into sX buffer 0 ----
    {
        const float4* x4 = (const float4*)x;
        float4* sX4 = (float4*)sX;
#pragma unroll
        for (int r = 0; r < 2; r++) {
            int i = tid + r * NT;
            sX4[i] = x4[((size_t)(i >> 6) * TT) * 64 + (i & 63)];
        }
    }
    __syncthreads();

    for (int p = 0; p <= TT; p++) {
        // ---- issue x(p+1) global loads early (latency hidden under the poll) ----
        float4 xv0, xv1;
        const bool xp = (p + 1 < TT);
        if (xp) {
            const float4* x4 = (const float4*)x;
            int i0 = tid, i1 = tid + NT;
            xv0 = x4[((size_t)(i0 >> 6) * TT + (p + 1)) * 64 + (i0 & 63)];
            xv1 = x4[((size_t)(i1 >> 6) * TT + (p + 1)) * 64 + (i1 & 63)];
        }

        // ---- tag-polling loads of h1(p-1) and h2(p-2) (data IS the barrier) ----
        // Expected tags: sA buffer p&1 -> tag p; sB buffer (p+1)&1 -> tag p-1 (0 at p<=1).
        const unsigned expA = (unsigned)p;
        const unsigned expB = (p >= 1) ? (unsigned)(p - 1) : 0u;
        const unsigned long long* srcA = g_hA + (p & 1) * (BB * HD);
        const unsigned long long* srcB = g_hB + ((p + 1) & 1) * (BB * HD);
        float va[16], vb[16];
        {
            bool ok;
            do {
                ok = true;
#pragma unroll
                for (int i = 0; i < 4; i++) {
#pragma unroll
                    for (int k = 0; k < 4; k++) {
                        const int e = tid * 4 + i * 1024 + k;
                        unsigned long long ua = ld_tag(srcA + e);
                        unsigned long long ub = ld_tag(srcB + e);
                        va[i * 4 + k] = __uint_as_float((unsigned)ua);
                        vb[i * 4 + k] = __uint_as_float((unsigned)ub);
                        ok = ok && ((unsigned)(ua >> 32) == expA)
                                && ((unsigned)(ub >> 32) == expB);
                    }
                }
            } while (!ok);
        }

        __syncthreads();   // prior period's dot reads of sA/sB/sX done everywhere

        // ---- STS staged data (conflict-free: lanes write consecutive 16B) ----
#pragma unroll
        for (int i = 0; i < 4; i++) {
            *(float4*)(sA + tid * 4 + i * 1024) =
                make_float4(va[i * 4], va[i * 4 + 1], va[i * 4 + 2], va[i * 4 + 3]);
            *(float4*)(sB + tid * 4 + i * 1024) =
                make_float4(vb[i * 4], vb[i * 4 + 1], vb[i * 4 + 2], vb[i * 4 + 3]);
        }
        if (xp) {
            float4* sX4 = (float4*)(sX + ((p + 1) & 1) * (BB * DI));
            sX4[tid] = xv0;
            sX4[tid + NT] = xv1;
        }
        __syncthreads();

        // ---- dots from register weights (single accumulator set) ----
        const bool active = L0 ? (p < TT) : (p > 0);
        if (active) {
            unsigned long long acc[32];
#pragma unroll
            for (int j = 0; j < 32; j++) acc[j] = 0ull;
            if (L0) {
                dotr<2, DI>(acc, wB, sX + (p & 1) * (BB * DI), lane);
                dotr<4, HD>(acc, wA, sA, lane);
            } else {
                dotr<4, HD>(acc, wA, sB, lane);
                dotr<4, HD>(acc, wB, sA, lane);
            }
            float v = hreduce(acc, lane);

            // gather the 4 gates of batch (lane&7)
            const int bsel = lane & 7;
            float vi = __shfl_sync(0xffffffffu, v, bsel);
            float vf = __shfl_sync(0xffffffffu, v, bsel + 8);
            float vg = __shfl_sync(0xffffffffu, v, bsel + 16);
            float vo = __shfl_sync(0xffffffffu, v, bsel + 24);

            if (lane < 8) {   // lane = batch
                float iv = sigm(vi + bs0);
                float fv = sigm(vf + bs1);
                float gv = tanh_mufu(vg + bs2);
                float ov = sigm(vo + bs3);
                float c = fv * creg + iv * gv;
                creg = c;
                float h = ov * fmaxf(c, 0.0f);   // custom relu nonlinearity
                if (L0) {
                    // publish h1(p) with tag p+1 into buffer (p+1)&1
                    st_tag(g_hA + ((p + 1) & 1) * (BB * HD) + lane * HD + jg, h,
                           (unsigned)(p + 1));
                    if (p == TT - 1) { hh[lane * HD + jg] = h; cc[lane * HD + jg] = c; }
                } else {
                    const int t1 = p - 1;
                    // publish h2(p-1) with tag p into buffer p&1
                    st_tag(g_hB + (p & 1) * (BB * HD) + lane * HD + jg, h, (unsigned)p);
                    __stcg(h2seq + ((size_t)lane * TT + t1) * HD + jg, h);
                    if (t1 == TT - 1) {
                        hh[BB * HD + lane * HD + jg] = h;
                        cc[BB * HD + lane * HD + jg] = c;
                    }
                }
            }
        }
    }
}

// ---------------- host launch ----------------
extern "C" void kernel_launch(void* const* d_in, const int* in_sizes, int n_in,
                              void* d_out, int out_size) {
    (void)in_sizes; (void)n_in; (void)out_size;
    const float* x   = (const float*)d_in[0];
    const float* w0w = (const float*)d_in[1];
    const float* w0b = (const float*)d_in[2];
    const float* u0w = (const float*)d_in[3];
    const float* u0b = (const float*)d_in[4];
    const float* w1w = (const float*)d_in[5];
    const float* w1b = (const float*)d_in[6];
    const float* u1w = (const float*)d_in[7];
    const float* u1b = (const float*)d_in[8];
    float* out = (float*)d_out;

    const size_t H2 = (size_t)BB * TT * HD;
    float* hh = out + H2;                     // [2, B, H]
    float* cc = hh + 2 * BB * HD;             // [2, B, H]

    const size_t smem = (size_t)(2 * BB * HD + 2 * BB * DI) * sizeof(float);  // 48 KB
    cudaFuncSetAttribute(lstm_fused_kernel, cudaFuncAttributeMaxDynamicSharedMemorySize,
                         (int)smem);

    init_kernel<<<32, 256>>>();
    lstm_fused_kernel<<<NB, NT, smem>>>(x, u0w, w0w, u0b, w0b,
                                        u1w, w1w, u1b, w1b,
                                        out, hh, cc);
}

// round 10
// speedup vs baseline: 1.6151x; 1.6151x over previous
#include <cuda_runtime.h>

#define NB 128   // persistent CTAs (1/SM, co-resident -> spin loops safe)
#define NT 256   // 8 warps
#define TT 2048
#define BB 8
#define HD 512
#define DI 256

// ---------------- device scratch (no cudaMalloc allowed) ----------------
__device__ float g_hA[2 * BB * HD];      // double-buffered h1 broadcast
__device__ float g_hB[2 * BB * HD];      // double-buffered h2 broadcast
__device__ unsigned g_flags[NB];         // periods completed per CTA (4 L2 lines)

__global__ void init_kernel() {
    int i = blockIdx.x * blockDim.x + threadIdx.x;
    int stride = gridDim.x * blockDim.x;
    if (i < NB) g_flags[i] = 0u;
    for (int k = i; k < 2 * BB * HD; k += stride) { g_hA[k] = 0.0f; g_hB[k] = 0.0f; }
}

__device__ __forceinline__ float tanh_mufu(float x) {
    float y;
    asm("tanh.approx.f32 %0, %1;" : "=f"(y) : "f"(x));
    return y;
}
__device__ __forceinline__ float sigm(float x) {
    return fmaf(0.5f, tanh_mufu(0.5f * x), 0.5f);
}

// Packed dual-FMA on the sm_103a f32x2 pipe.
__device__ __forceinline__ void ffma2(unsigned long long& d, unsigned long long a,
                                      unsigned long long b) {
    asm("fma.rn.f32x2 %0, %1, %2, %0;" : "+l"(d) : "l"(a), "l"(b));
}

// Wait until every CTA has completed >= target periods (4 L2 lines, acquire).
__device__ __forceinline__ void poll_flags(int lane, unsigned target) {
    const unsigned* f = g_flags + lane;
    bool ok;
    do {
        unsigned a, b, c, d;
        asm volatile("ld.acquire.gpu.global.b32 %0, [%1];" : "=r"(a) : "l"(f)      : "memory");
        asm volatile("ld.acquire.gpu.global.b32 %0, [%1];" : "=r"(b) : "l"(f + 32) : "memory");
        asm volatile("ld.acquire.gpu.global.b32 %0, [%1];" : "=r"(c) : "l"(f + 64) : "memory");
        asm volatile("ld.acquire.gpu.global.b32 %0, [%1];" : "=r"(d) : "l"(f + 96) : "memory");
        ok = (a >= target) && (b >= target) && (c >= target) && (d >= target);
    } while (!__all_sync(0xffffffffu, ok));
}

// Register-weight dot: acc[g*8+b] += wgt[it][g] (lane's k-slice) * src[b].
template <int NIT, int STR>
__device__ __forceinline__ void dotr(unsigned long long* acc,
                                     const ulonglong2 (*wgt)[4],
                                     const float* __restrict__ src, int lane) {
#pragma unroll
    for (int it = 0; it < NIT; it++) {
        const float* s = src + it * 128 + lane * 4;
#pragma unroll
        for (int b = 0; b < 8; b++) {
            ulonglong2 v = *(const ulonglong2*)(s + b * STR);
#pragma unroll
            for (int g = 0; g < 4; g++) {
                ffma2(acc[g * 8 + b], wgt[it][g].x, v.x);
                ffma2(acc[g * 8 + b], wgt[it][g].y, v.y);
            }
        }
    }
}

// Shared-weight dot: weights streamed from smem (rows ro0..ro0+3 of mat).
template <int KP>
__device__ __forceinline__ void dots(unsigned long long* acc,
                                     const float* __restrict__ mat,
                                     const float* __restrict__ src, int ro0, int lane) {
#pragma unroll
    for (int it = 0; it < KP / 128; it++) {
        const int kb = it * 128 + lane * 4;
        ulonglong2 m[4];
#pragma unroll
        for (int r = 0; r < 4; r++)
            m[r] = *(const ulonglong2*)(mat + (ro0 + r) * KP + kb);
#pragma unroll
        for (int b = 0; b < 8; b++) {
            ulonglong2 v = *(const ulonglong2*)(src + b * KP + kb);
#pragma unroll
            for (int r = 0; r < 4; r++) {
                ffma2(acc[r * 8 + b], m[r].x, v.x);
                ffma2(acc[r * 8 + b], m[r].y, v.y);
            }
        }
    }
}

// Horizontal f32x2 add + 31-shuffle reduce-scatter.
// Lane l ends owning the total for (gate = l>>3, batch = l&7).
__device__ __forceinline__ float hreduce(const unsigned long long* acc, int lane) {
    float av[32];
#pragma unroll
    for (int j = 0; j < 32; j++) {
        unsigned lo, hi;
        asm("mov.b64 {%0,%1}, %2;" : "=r"(lo), "=r"(hi) : "l"(acc[j]));
        av[j] = __uint_as_float(lo) + __uint_as_float(hi);
    }
#pragma unroll
    for (int m = 16; m > 0; m >>= 1) {
        const bool hi = (lane & m) != 0;
#pragma unroll
        for (int j = 0; j < m; j++) {
            float sendv = hi ? av[j] : av[j + m];
            float other = __shfl_xor_sync(0xffffffffu, sendv, m);
            av[j] = (hi ? av[j + m] : av[j]) + other;
        }
    }
    return av[0];
}

// Fused 2-layer wavefront: period p = layer0 step p + layer1 step p-1.
// Warp = (layer, column). U weights in registers; W weights in shared
// (keeps regs under the spill threshold). Flag barrier, single accumulator.
__global__ void __launch_bounds__(NT, 1) lstm_fused_kernel(
    const float* __restrict__ x,
    const float* __restrict__ u0W, const float* __restrict__ w0W,
    const float* __restrict__ u0b, const float* __restrict__ w0b,
    const float* __restrict__ u1W, const float* __restrict__ w1W,
    const float* __restrict__ u1b, const float* __restrict__ w1b,
    float* __restrict__ h2seq, float* __restrict__ hh, float* __restrict__ cc)
{
    extern __shared__ float sm[];
    float* sW0 = sm;                  // 16 x 256 (rows jl*4+g)
    float* sW1 = sW0 + 16 * DI;       // 16 x 512
    float* sA  = sW1 + 16 * HD;       // 8*512  h1(p-1) stage
    float* sB  = sA + BB * HD;        // 8*512  h2(p-2) stage
    float* sX  = sB + BB * HD;        // 2 x 8*256  x double buffer

    const int tid  = threadIdx.x;
    const int bid  = blockIdx.x;
    const int w    = tid >> 5;
    const int lane = tid & 31;
    const bool L0  = (w < 4);
    const int jl   = L0 ? w : (w - 4);
    const int jg   = bid * 4 + jl;

    // ---- W weights into shared (local row jl*4+g <-> global row g*HD+jg) ----
    for (int idx = tid; idx < 16 * DI; idx += NT) {
        int ro = idx >> 8, k = idx & (DI - 1);
        sW0[idx] = w0W[((ro & 3) * HD + bid * 4 + (ro >> 2)) * DI + k];
    }
    for (int idx = tid; idx < 16 * HD; idx += NT) {
        int ro = idx >> 9, k = idx & (HD - 1);
        sW1[idx] = w1W[((ro & 3) * HD + bid * 4 + (ro >> 2)) * HD + k];
    }

    // ---- U weights into registers (constant for all 2048 steps) ----
    ulonglong2 wA[4][4];   // [k-iter][gate]
    {
        const float* Up = L0 ? u0W : u1W;
#pragma unroll
        for (int it = 0; it < 4; it++)
#pragma unroll
            for (int g = 0; g < 4; g++)
                wA[it][g] = *(const ulonglong2*)(Up + (size_t)(g * HD + jg) * HD
                                                 + it * 128 + lane * 4);
    }
    float bs0, bs1, bs2, bs3;
    {
        const float* ubp = L0 ? u0b : u1b;
        const float* wbp = L0 ? w0b : w1b;
        bs0 = ubp[0 * HD + jg] + wbp[0 * HD + jg];
        bs1 = ubp[1 * HD + jg] + wbp[1 * HD + jg];
        bs2 = ubp[2 * HD + jg] + wbp[2 * HD + jg];
        bs3 = ubp[3 * HD + jg] + wbp[3 * HD + jg];
    }
    float creg = 0.0f;   // cell state (column jg, batch=lane) on lanes 0-7

    // ---- stage x(0) into sX buffer 0 ----
    {
        const float4* x4 = (const float4*)x;
        float4* sX4 = (float4*)sX;
#pragma unroll
        for (int r = 0; r < 2; r++) {
            int i = tid + r * NT;
            sX4[i] = x4[((size_t)(i >> 6) * TT) * 64 + (i & 63)];
        }
    }
    __syncthreads();

    for (int p = 0; p <= TT; p++) {
        // L2 prefetch of x(p+1)
        if (p + 1 < TT && tid < 64) {
            const float* pf = x + ((size_t)(tid >> 3) * TT + (p + 1)) * DI + (tid & 7) * 32;
            asm volatile("prefetch.global.L2 [%0];" :: "l"(pf));
        }
        // issue x(p+1) loads early (L2-resident via prefetch from last period)
        float4 xv0, xv1;
        const bool xp = (p + 1 < TT);
        if (xp) {
            const float4* x4 = (const float4*)x;
            int i0 = tid, i1 = tid + NT;
            xv0 = x4[((size_t)(i0 >> 6) * TT + (p + 1)) * 64 + (i0 & 63)];
            xv1 = x4[((size_t)(i1 >> 6) * TT + (p + 1)) * 64 + (i1 & 63)];
        }

        // ---- phase 1: L0 warps fold W0*x into acc; warp 3 then polls ----
        unsigned long long acc[32];
#pragma unroll
        for (int j = 0; j < 32; j++) acc[j] = 0ull;
        if (L0 && p < TT)
            dots<DI>(acc, sW0, sX + (p & 1) * (BB * DI), jl * 4, lane);
        if (w == 3) poll_flags(lane, (unsigned)p);
        __syncthreads();

        // ---- phase 2: stage recurrent broadcasts from L2 ----
        {
            const float4* a4 = (const float4*)(g_hA + (p & 1) * (BB * HD));
            const float4* b4 = (const float4*)(g_hB + ((p + 1) & 1) * (BB * HD));
            float4 va[4], vb[4];
#pragma unroll
            for (int r = 0; r < 4; r++) {
                va[r] = __ldcg(a4 + tid + r * NT);
                vb[r] = __ldcg(b4 + tid + r * NT);
            }
            float4* sA4 = (float4*)sA;
            float4* sB4 = (float4*)sB;
#pragma unroll
            for (int r = 0; r < 4; r++) {
                sA4[tid + r * NT] = va[r];
                sB4[tid + r * NT] = vb[r];
            }
            if (xp) {
                float4* sX4 = (float4*)(sX + ((p + 1) & 1) * (BB * DI));
                sX4[tid] = xv0;
                sX4[tid + NT] = xv1;
            }
        }
        __syncthreads();

        // ---- phase 3: recurrent dots + cell update ----
        const bool active = L0 ? (p < TT) : (p > 0);
        if (active) {
            if (L0) {
                dotr<4, HD>(acc, wA, sA, lane);
            } else {
                dotr<4, HD>(acc, wA, sB, lane);
                dots<HD>(acc, sW1, sA, jl * 4, lane);
            }
            float v = hreduce(acc, lane);

            const int bsel = lane & 7;
            float vi = __shfl_sync(0xffffffffu, v, bsel);
            float vf = __shfl_sync(0xffffffffu, v, bsel + 8);
            float vg = __shfl_sync(0xffffffffu, v, bsel + 16);
            float vo = __shfl_sync(0xffffffffu, v, bsel + 24);

            if (lane < 8) {   // lane = batch
                float iv = sigm(vi + bs0);
                float fv = sigm(vf + bs1);
                float gv = tanh_mufu(vg + bs2);
                float ov = sigm(vo + bs3);
                float c = fv * creg + iv * gv;
                creg = c;
                float h = ov * fmaxf(c, 0.0f);   // custom relu nonlinearity
                if (L0) {
                    __stcg(g_hA + ((p + 1) & 1) * (BB * HD) + lane * HD + jg, h);
                    if (p == TT - 1) { hh[lane * HD + jg] = h; cc[lane * HD + jg] = c; }
                } else {
                    const int t1 = p - 1;
                    __stcg(g_hB + (p & 1) * (BB * HD) + lane * HD + jg, h);
                    __stcg(h2seq + ((size_t)lane * TT + t1) * HD + jg, h);
                    if (t1 == TT - 1) {
                        hh[BB * HD + lane * HD + jg] = h;
                        cc[BB * HD + lane * HD + jg] = c;
                    }
                }
            }
        }

        // ---- publish completion of period p ----
        __syncthreads();
        if (tid == 0) {
            unsigned v = (unsigned)(p + 1);
            asm volatile("st.release.gpu.global.b32 [%0], %1;"
                         :: "l"(g_flags + bid), "r"(v) : "memory");
        }
    }
}

// ---------------- host launch ----------------
extern "C" void kernel_launch(void* const* d_in, const int* in_sizes, int n_in,
                              void* d_out, int out_size) {
    (void)in_sizes; (void)n_in; (void)out_size;
    const float* x   = (const float*)d_in[0];
    const float* w0w = (const float*)d_in[1];
    const float* w0b = (const float*)d_in[2];
    const float* u0w = (const float*)d_in[3];
    const float* u0b = (const float*)d_in[4];
    const float* w1w = (const float*)d_in[5];
    const float* w1b = (const float*)d_in[6];
    const float* u1w = (const float*)d_in[7];
    const float* u1b = (const float*)d_in[8];
    float* out = (float*)d_out;

    const size_t H2 = (size_t)BB * TT * HD;
    float* hh = out + H2;                     // [2, B, H]
    float* cc = hh + 2 * BB * HD;             // [2, B, H]

    const size_t smem = (size_t)(16 * DI + 16 * HD + 2 * BB * HD + 2 * BB * DI)
                        * sizeof(float);      // 96 KB
    cudaFuncSetAttribute(lstm_fused_kernel, cudaFuncAttributeMaxDynamicSharedMemorySize,
                         (int)smem);

    init_kernel<<<32, 256>>>();
    lstm_fused_kernel<<<NB, NT, smem>>>(x, u0w, w0w, u0b, w0b,
                                        u1w, w1w, u1b, w1b,
                                        out, hh, cc);
}

// round 11
// speedup vs baseline: 1.6335x; 1.0114x over previous
#include <cuda_runtime.h>

#define NB 128   // persistent CTAs (1/SM, co-resident -> spin loops safe)
#define NT 256   // 8 warps
#define TT 2048
#define BB 8
#define HD 512
#define DI 256

// ---------------- device scratch (no cudaMalloc allowed) ----------------
__device__ float g_hA[2 * BB * HD];      // double-buffered h1 broadcast
__device__ float g_hB[2 * BB * HD];      // double-buffered h2 broadcast
__device__ unsigned g_flagA[NB];         // L0 periods completed per CTA
__device__ unsigned g_flagB[NB];         // L1 periods completed per CTA

__global__ void init_kernel() {
    int i = blockIdx.x * blockDim.x + threadIdx.x;
    int stride = gridDim.x * blockDim.x;
    if (i < NB) { g_flagA[i] = 0u; g_flagB[i] = 0u; }
    for (int k = i; k < 2 * BB * HD; k += stride) { g_hA[k] = 0.0f; g_hB[k] = 0.0f; }
}

__device__ __forceinline__ float tanh_mufu(float x) {
    float y;
    asm("tanh.approx.f32 %0, %1;" : "=f"(y) : "f"(x));
    return y;
}
__device__ __forceinline__ float sigm(float x) {
    return fmaf(0.5f, tanh_mufu(0.5f * x), 0.5f);
}

// Packed dual-FMA on the sm_103a f32x2 pipe.
__device__ __forceinline__ void ffma2(unsigned long long& d, unsigned long long a,
                                      unsigned long long b) {
    asm("fma.rn.f32x2 %0, %1, %2, %0;" : "+l"(d) : "l"(a), "l"(b));
}

// Wait until every CTA has published period >= target on BOTH flag arrays.
__device__ __forceinline__ void poll_flags(int lane, unsigned target) {
    const unsigned* fa = g_flagA + lane;
    const unsigned* fb = g_flagB + lane;
    bool ok;
    do {
        unsigned a0, a1, a2, a3, b0, b1, b2, b3;
        asm volatile("ld.acquire.gpu.global.b32 %0, [%1];" : "=r"(a0) : "l"(fa)      : "memory");
        asm volatile("ld.acquire.gpu.global.b32 %0, [%1];" : "=r"(a1) : "l"(fa + 32) : "memory");
        asm volatile("ld.acquire.gpu.global.b32 %0, [%1];" : "=r"(a2) : "l"(fa + 64) : "memory");
        asm volatile("ld.acquire.gpu.global.b32 %0, [%1];" : "=r"(a3) : "l"(fa + 96) : "memory");
        asm volatile("ld.acquire.gpu.global.b32 %0, [%1];" : "=r"(b0) : "l"(fb)      : "memory");
        asm volatile("ld.acquire.gpu.global.b32 %0, [%1];" : "=r"(b1) : "l"(fb + 32) : "memory");
        asm volatile("ld.acquire.gpu.global.b32 %0, [%1];" : "=r"(b2) : "l"(fb + 64) : "memory");
        asm volatile("ld.acquire.gpu.global.b32 %0, [%1];" : "=r"(b3) : "l"(fb + 96) : "memory");
        ok = (a0 >= target) && (a1 >= target) && (a2 >= target) && (a3 >= target)
          && (b0 >= target) && (b1 >= target) && (b2 >= target) && (b3 >= target);
    } while (!__all_sync(0xffffffffu, ok));
}

// Register-weight dot: acc[g*8+b] += wgt[it][g] (lane's k-slice) * src[b].
template <int NIT, int STR>
__device__ __forceinline__ void dotr(unsigned long long* acc,
                                     const ulonglong2 (*wgt)[4],
                                     const float* __restrict__ src, int lane) {
#pragma unroll
    for (int it = 0; it < NIT; it++) {
        const float* s = src + it * 128 + lane * 4;
#pragma unroll
        for (int b = 0; b < 8; b++) {
            ulonglong2 v = *(const ulonglong2*)(s + b * STR);
#pragma unroll
            for (int g = 0; g < 4; g++) {
                ffma2(acc[g * 8 + b], wgt[it][g].x, v.x);
                ffma2(acc[g * 8 + b], wgt[it][g].y, v.y);
            }
        }
    }
}

// Shared-weight dot: weights streamed from smem (rows ro0..ro0+3 of mat).
template <int KP>
__device__ __forceinline__ void dots(unsigned long long* acc,
                                     const float* __restrict__ mat,
                                     const float* __restrict__ src, int ro0, int lane) {
#pragma unroll
    for (int it = 0; it < KP / 128; it++) {
        const int kb = it * 128 + lane * 4;
        ulonglong2 m[4];
#pragma unroll
        for (int r = 0; r < 4; r++)
            m[r] = *(const ulonglong2*)(mat + (ro0 + r) * KP + kb);
#pragma unroll
        for (int b = 0; b < 8; b++) {
            ulonglong2 v = *(const ulonglong2*)(src + b * KP + kb);
#pragma unroll
            for (int r = 0; r < 4; r++) {
                ffma2(acc[r * 8 + b], m[r].x, v.x);
                ffma2(acc[r * 8 + b], m[r].y, v.y);
            }
        }
    }
}

// Horizontal f32x2 add + 31-shuffle reduce-scatter.
// Lane l ends owning the total for (gate = l>>3, batch = l&7).
__device__ __forceinline__ float hreduce(const unsigned long long* acc, int lane) {
    float av[32];
#pragma unroll
    for (int j = 0; j < 32; j++) {
        unsigned lo, hi;
        asm("mov.b64 {%0,%1}, %2;" : "=r"(lo), "=r"(hi) : "l"(acc[j]));
        av[j] = __uint_as_float(lo) + __uint_as_float(hi);
    }
#pragma unroll
    for (int m = 16; m > 0; m >>= 1) {
        const bool hi = (lane & m) != 0;
#pragma unroll
        for (int j = 0; j < m; j++) {
            float sendv = hi ? av[j] : av[j + m];
            float other = __shfl_xor_sync(0xffffffffu, sendv, m);
            av[j] = (hi ? av[j + m] : av[j]) + other;
        }
    }
    return av[0];
}

// Fused 2-layer wavefront: period p = layer0 step p + layer1 step p-1.
// Warp = (layer, column). U0/U1/W0 in registers; W1 streamed from shared
// (keeps every path's register peak under the spill threshold).
// L0 and L1 publish completion independently (split flags).
__global__ void __launch_bounds__(NT, 1) lstm_fused_kernel(
    const float* __restrict__ x,
    const float* __restrict__ u0W, const float* __restrict__ w0W,
    const float* __restrict__ u0b, const float* __restrict__ w0b,
    const float* __restrict__ u1W, const float* __restrict__ w1W,
    const float* __restrict__ u1b, const float* __restrict__ w1b,
    float* __restrict__ h2seq, float* __restrict__ hh, float* __restrict__ cc)
{
    extern __shared__ float sm[];
    float* sW1 = sm;                  // 16 x 512 (rows jl*4+g) W1 slice
    float* sA  = sW1 + 16 * HD;       // 8*512  h1(p-1) stage
    float* sB  = sA + BB * HD;        // 8*512  h2(p-2) stage
    float* sX  = sB + BB * HD;        // 2 x 8*256  x double buffer

    const int tid  = threadIdx.x;
    const int bid  = blockIdx.x;
    const int w    = tid >> 5;
    const int lane = tid & 31;
    const bool L0  = (w < 4);
    const int jl   = L0 ? w : (w - 4);
    const int jg   = bid * 4 + jl;

    // ---- W1 into shared (local row jl*4+g <-> global row g*HD + bid*4+jl) ----
    for (int idx = tid; idx < 16 * HD; idx += NT) {
        int ro = idx >> 9, k = idx & (HD - 1);
        sW1[idx] = w1W[((size_t)(ro & 3) * HD + bid * 4 + (ro >> 2)) * HD + k];
    }

    // ---- U weights (both layers) + W0 (L0 only) into registers ----
    ulonglong2 wA[4][4];   // recurrent U: [k-iter][gate]
    ulonglong2 wB[2][4];   // W0 (L0 warps only), K=256
    {
        const float* Up = L0 ? u0W : u1W;
#pragma unroll
        for (int it = 0; it < 4; it++)
#pragma unroll
            for (int g = 0; g < 4; g++)
                wA[it][g] = *(const ulonglong2*)(Up + (size_t)(g * HD + jg) * HD
                                                 + it * 128 + lane * 4);
        if (L0) {
#pragma unroll
            for (int it = 0; it < 2; it++)
#pragma unroll
                for (int g = 0; g < 4; g++)
                    wB[it][g] = *(const ulonglong2*)(w0W + (size_t)(g * HD + jg) * DI
                                                     + it * 128 + lane * 4);
        }
    }
    float bs0, bs1, bs2, bs3;
    {
        const float* ubp = L0 ? u0b : u1b;
        const float* wbp = L0 ? w0b : w1b;
        bs0 = ubp[0 * HD + jg] + wbp[0 * HD + jg];
        bs1 = ubp[1 * HD + jg] + wbp[1 * HD + jg];
        bs2 = ubp[2 * HD + jg] + wbp[2 * HD + jg];
        bs3 = ubp[3 * HD + jg] + wbp[3 * HD + jg];
    }
    float creg = 0.0f;   // cell state (column jg, batch=lane) on lanes 0-7

    // ---- stage x(0) into sX buffer 0 ----
    {
        const float4* x4 = (const float4*)x;
        float4* sX4 = (float4*)sX;
#pragma unroll
        for (int r = 0; r < 2; r++) {
            int i = tid + r * NT;
            sX4[i] = x4[((size_t)(i >> 6) * TT) * 64 + (i & 63)];
        }
    }
    __syncthreads();

    for (int p = 0; p <= TT; p++) {
        // L2 prefetch of x(p+1), then issue x(p+1) loads early
        if (p + 1 < TT && tid < 64) {
            const float* pf = x + ((size_t)(tid >> 3) * TT + (p + 1)) * DI + (tid & 7) * 32;
            asm volatile("prefetch.global.L2 [%0];" :: "l"(pf));
        }
        float4 xv0, xv1;
        const bool xp = (p + 1 < TT);
        if (xp) {
            const float4* x4 = (const float4*)x;
            int i0 = tid, i1 = tid + NT;
            xv0 = x4[((size_t)(i0 >> 6) * TT + (p + 1)) * 64 + (i0 & 63)];
            xv1 = x4[((size_t)(i1 >> 6) * TT + (p + 1)) * 64 + (i1 & 63)];
        }

        // ---- phase 1: L0 warps do W0*x and pre-reduce to scalar r0 (keeps
        //      acc dead across staging); warp 3 polls period-p barrier ----
        float r0 = 0.0f;
        if (L0 && p < TT) {
            unsigned long long accx[32];
#pragma unroll
            for (int j = 0; j < 32; j++) accx[j] = 0ull;
            dotr<2, DI>(accx, wB, sX + (p & 1) * (BB * DI), lane);
            r0 = hreduce(accx, lane);
        }
        if (w == 3) poll_flags(lane, (unsigned)p);
        __syncthreads();

        // ---- phase 2: stage recurrent broadcasts from L2 ----
        {
            const float4* a4 = (const float4*)(g_hA + (p & 1) * (BB * HD));
            const float4* b4 = (const float4*)(g_hB + ((p + 1) & 1) * (BB * HD));
            float4 va[4], vb[4];
#pragma unroll
            for (int r = 0; r < 4; r++) {
                va[r] = __ldcg(a4 + tid + r * NT);
                vb[r] = __ldcg(b4 + tid + r * NT);
            }
            float4* sA4 = (float4*)sA;
            float4* sB4 = (float4*)sB;
#pragma unroll
            for (int r = 0; r < 4; r++) {
                sA4[tid + r * NT] = va[r];
                sB4[tid + r * NT] = vb[r];
            }
            if (xp) {
                float4* sX4 = (float4*)(sX + ((p + 1) & 1) * (BB * DI));
                sX4[tid] = xv0;
                sX4[tid + NT] = xv1;
            }
        }
        __syncthreads();

        // ---- phase 3: recurrent dots + cell update + split publish ----
        if (L0) {
            if (p < TT) {
                unsigned long long acc[32];
#pragma unroll
                for (int j = 0; j < 32; j++) acc[j] = 0ull;
                dotr<4, HD>(acc, wA, sA, lane);
                float v = hreduce(acc, lane) + r0;

                const int bsel = lane & 7;
                float vi = __shfl_sync(0xffffffffu, v, bsel);
                float vf = __shfl_sync(0xffffffffu, v, bsel + 8);
                float vg = __shfl_sync(0xffffffffu, v, bsel + 16);
                float vo = __shfl_sync(0xffffffffu, v, bsel + 24);
                if (lane < 8) {
                    float iv = sigm(vi + bs0);
                    float fv = sigm(vf + bs1);
                    float gv = tanh_mufu(vg + bs2);
                    float ov = sigm(vo + bs3);
                    float c = fv * creg + iv * gv;
                    creg = c;
                    float h = ov * fmaxf(c, 0.0f);   // custom relu nonlinearity
                    __stcg(g_hA + ((p + 1) & 1) * (BB * HD) + lane * HD + jg, h);
                    if (p == TT - 1) { hh[lane * HD + jg] = h; cc[lane * HD + jg] = c; }
                }
            }
            // publish L0 completion of period p (h1(p) visible)
            asm volatile("bar.sync 1, 128;" ::: "memory");
            if (tid == 0) {
                unsigned v = (unsigned)(p + 1);
                asm volatile("st.release.gpu.global.b32 [%0], %1;"
                             :: "l"(g_flagA + bid), "r"(v) : "memory");
            }
        } else {
            if (p > 0) {
                unsigned long long acc[32];
#pragma unroll
                for (int j = 0; j < 32; j++) acc[j] = 0ull;
                dotr<4, HD>(acc, wA, sB, lane);
                dots<HD>(acc, sW1, sA, jl * 4, lane);
                float v = hreduce(acc, lane);

                const int bsel = lane & 7;
                float vi = __shfl_sync(0xffffffffu, v, bsel);
                float vf = __shfl_sync(0xffffffffu, v, bsel + 8);
                float vg = __shfl_sync(0xffffffffu, v, bsel + 16);
                float vo = __shfl_sync(0xffffffffu, v, bsel + 24);
                if (lane < 8) {
                    const int t1 = p - 1;
                    float iv = sigm(vi + bs0);
                    float fv = sigm(vf + bs1);
                    float gv = tanh_mufu(vg + bs2);
                    float ov = sigm(vo + bs3);
                    float c = fv * creg + iv * gv;
                    creg = c;
                    float h = ov * fmaxf(c, 0.0f);
                    __stcg(g_hB + (p & 1) * (BB * HD) + lane * HD + jg, h);
                    __stcg(h2seq + ((size_t)lane * TT + t1) * HD + jg, h);
                    if (t1 == TT - 1) {
                        hh[BB * HD + lane * HD + jg] = h;
                        cc[BB * HD + lane * HD + jg] = c;
                    }
                }
            }
            // publish L1 completion of period p (h2(p-1) visible)
            asm volatile("bar.sync 2, 128;" ::: "memory");
            if (tid == 128) {
                unsigned v = (unsigned)(p + 1);
                asm volatile("st.release.gpu.global.b32 [%0], %1;"
                             :: "l"(g_flagB + bid), "r"(v) : "memory");
            }
        }
    }
}

// ---------------- host launch ----------------
extern "C" void kernel_launch(void* const* d_in, const int* in_sizes, int n_in,
                              void* d_out, int out_size) {
    (void)in_sizes; (void)n_in; (void)out_size;
    const float* x   = (const float*)d_in[0];
    const float* w0w = (const float*)d_in[1];
    const float* w0b = (const float*)d_in[2];
    const float* u0w = (const float*)d_in[3];
    const float* u0b = (const float*)d_in[4];
    const float* w1w = (const float*)d_in[5];
    const float* w1b = (const float*)d_in[6];
    const float* u1w = (const float*)d_in[7];
    const float* u1b = (const float*)d_in[8];
    float* out = (float*)d_out;

    const size_t H2 = (size_t)BB * TT * HD;
    float* hh = out + H2;                     // [2, B, H]
    float* cc = hh + 2 * BB * HD;             // [2, B, H]

    const size_t smem = (size_t)(16 * HD + 2 * BB * HD + 2 * BB * DI)
                        * sizeof(float);      // 80 KB
    cudaFuncSetAttribute(lstm_fused_kernel, cudaFuncAttributeMaxDynamicSharedMemorySize,
                         (int)smem);

    init_kernel<<<32, 256>>>();
    lstm_fused_kernel<<<NB, NT, smem>>>(x, u0w, w0w, u0b, w0b,
                                        u1w, w1w, u1b, w1b,
                                        out, hh, cc);
}

// round 12
// speedup vs baseline: 2.3454x; 1.4359x over previous
#include <cuda_runtime.h>

#define NB 128   // persistent CTAs (1/SM, co-resident -> spin loops safe)
#define NT 256   // 8 warps
#define TT 2048
#define BB 8
#define HD 512
#define DI 256

// ---------------- device scratch (no cudaMalloc allowed) ----------------
__device__ float g_hA[2 * BB * HD];      // double-buffered h1 broadcast
__device__ float g_hB[2 * BB * HD];      // double-buffered h2 broadcast
__device__ unsigned g_flags[NB];         // periods completed per CTA (4 L2 lines)

__global__ void init_kernel() {
    int i = blockIdx.x * blockDim.x + threadIdx.x;
    int stride = gridDim.x * blockDim.x;
    if (i < NB) g_flags[i] = 0u;
    for (int k = i; k < 2 * BB * HD; k += stride) { g_hA[k] = 0.0f; g_hB[k] = 0.0f; }
}

__device__ __forceinline__ float tanh_mufu(float x) {
    float y;
    asm("tanh.approx.f32 %0, %1;" : "=f"(y) : "f"(x));
    return y;
}
__device__ __forceinline__ float sigm(float x) {
    return fmaf(0.5f, tanh_mufu(0.5f * x), 0.5f);
}

// Packed dual-FMA on the sm_103a f32x2 pipe.
__device__ __forceinline__ void ffma2(unsigned long long& d, unsigned long long a,
                                      unsigned long long b) {
    asm("fma.rn.f32x2 %0, %1, %2, %0;" : "+l"(d) : "l"(a), "l"(b));
}

// Wait until every CTA has completed >= target periods (4 L2 lines, acquire).
__device__ __forceinline__ void poll_flags(int lane, unsigned target) {
    const unsigned* f = g_flags + lane;
    bool ok;
    do {
        unsigned a, b, c, d;
        asm volatile("ld.acquire.gpu.global.b32 %0, [%1];" : "=r"(a) : "l"(f)      : "memory");
        asm volatile("ld.acquire.gpu.global.b32 %0, [%1];" : "=r"(b) : "l"(f + 32) : "memory");
        asm volatile("ld.acquire.gpu.global.b32 %0, [%1];" : "=r"(c) : "l"(f + 64) : "memory");
        asm volatile("ld.acquire.gpu.global.b32 %0, [%1];" : "=r"(d) : "l"(f + 96) : "memory");
        ok = (a >= target) && (b >= target) && (c >= target) && (d >= target);
    } while (!__all_sync(0xffffffffu, ok));
}

// Register-weight dot: acc[g*8+b] += wgt[it][g] (lane's k-slice) * src[b].
template <int NIT, int STR>
__device__ __forceinline__ void dotr(unsigned long long* acc,
                                     const ulonglong2 (*wgt)[4],
                                     const float* __restrict__ src, int lane) {
#pragma unroll
    for (int it = 0; it < NIT; it++) {
        const float* s = src + it * 128 + lane * 4;
#pragma unroll
        for (int b = 0; b < 8; b++) {
            ulonglong2 v = *(const ulonglong2*)(s + b * STR);
#pragma unroll
            for (int g = 0; g < 4; g++) {
                ffma2(acc[g * 8 + b], wgt[it][g].x, v.x);
                ffma2(acc[g * 8 + b], wgt[it][g].y, v.y);
            }
        }
    }
}

// Shared-weight dot: weights streamed from smem (rows ro0..ro0+3 of mat).
template <int KP>
__device__ __forceinline__ void dots(unsigned long long* acc,
                                     const float* __restrict__ mat,
                                     const float* __restrict__ src, int ro0, int lane) {
#pragma unroll
    for (int it = 0; it < KP / 128; it++) {
        const int kb = it * 128 + lane * 4;
        ulonglong2 m[4];
#pragma unroll
        for (int r = 0; r < 4; r++)
            m[r] = *(const ulonglong2*)(mat + (ro0 + r) * KP + kb);
#pragma unroll
        for (int b = 0; b < 8; b++) {
            ulonglong2 v = *(const ulonglong2*)(src + b * KP + kb);
#pragma unroll
            for (int r = 0; r < 4; r++) {
                ffma2(acc[r * 8 + b], m[r].x, v.x);
                ffma2(acc[r * 8 + b], m[r].y, v.y);
            }
        }
    }
}

// Horizontal f32x2 add + 31-shuffle reduce-scatter.
// Lane l ends owning the total for (gate = l>>3, batch = l&7).
__device__ __forceinline__ float hreduce(const unsigned long long* acc, int lane) {
    float av[32];
#pragma unroll
    for (int j = 0; j < 32; j++) {
        unsigned lo, hi;
        asm("mov.b64 {%0,%1}, %2;" : "=r"(lo), "=r"(hi) : "l"(acc[j]));
        av[j] = __uint_as_float(lo) + __uint_as_float(hi);
    }
#pragma unroll
    for (int m = 16; m > 0; m >>= 1) {
        const bool hi = (lane & m) != 0;
#pragma unroll
        for (int j = 0; j < m; j++) {
            float sendv = hi ? av[j] : av[j + m];
            float other = __shfl_xor_sync(0xffffffffu, sendv, m);
            av[j] = (hi ? av[j + m] : av[j]) + other;
        }
    }
    return av[0];
}

// Fused 2-layer wavefront: period p = layer0 step p + layer1 step p-1.
// Warp = (layer, column). U0/U1/W0 in registers; W1 streamed from shared.
// Single flag barrier (R4 protocol), streamed staging to keep regs low.
__global__ void __launch_bounds__(NT, 1) lstm_fused_kernel(
    const float* __restrict__ x,
    const float* __restrict__ u0W, const float* __restrict__ w0W,
    const float* __restrict__ u0b, const float* __restrict__ w0b,
    const float* __restrict__ u1W, const float* __restrict__ w1W,
    const float* __restrict__ u1b, const float* __restrict__ w1b,
    float* __restrict__ h2seq, float* __restrict__ hh, float* __restrict__ cc)
{
    extern __shared__ float sm[];
    float* sW1 = sm;                  // 16 x 512 (rows jl*4+g) W1 slice
    float* sA  = sW1 + 16 * HD;       // 8*512  h1(p-1) stage
    float* sB  = sA + BB * HD;        // 8*512  h2(p-2) stage
    float* sX  = sB + BB * HD;        // 2 x 8*256  x double buffer

    const int tid  = threadIdx.x;
    const int bid  = blockIdx.x;
    const int w    = tid >> 5;
    const int lane = tid & 31;
    const bool L0  = (w < 4);
    const int jl   = L0 ? w : (w - 4);
    const int jg   = bid * 4 + jl;

    // ---- W1 into shared (local row jl*4+g <-> global row g*HD + bid*4+jl) ----
    for (int idx = tid; idx < 16 * HD; idx += NT) {
        int ro = idx >> 9, k = idx & (HD - 1);
        sW1[idx] = w1W[((size_t)(ro & 3) * HD + bid * 4 + (ro >> 2)) * HD + k];
    }

    // ---- U weights (both layers) + W0 (L0 only) into registers ----
    ulonglong2 wA[4][4];   // recurrent U: [k-iter][gate]
    ulonglong2 wB[2][4];   // W0 (L0 warps only), K=256
    {
        const float* Up = L0 ? u0W : u1W;
#pragma unroll
        for (int it = 0; it < 4; it++)
#pragma unroll
            for (int g = 0; g < 4; g++)
                wA[it][g] = *(const ulonglong2*)(Up + (size_t)(g * HD + jg) * HD
                                                 + it * 128 + lane * 4);
        if (L0) {
#pragma unroll
            for (int it = 0; it < 2; it++)
#pragma unroll
                for (int g = 0; g < 4; g++)
                    wB[it][g] = *(const ulonglong2*)(w0W + (size_t)(g * HD + jg) * DI
                                                     + it * 128 + lane * 4);
        }
    }
    float bs0, bs1, bs2, bs3;
    {
        const float* ubp = L0 ? u0b : u1b;
        const float* wbp = L0 ? w0b : w1b;
        bs0 = ubp[0 * HD + jg] + wbp[0 * HD + jg];
        bs1 = ubp[1 * HD + jg] + wbp[1 * HD + jg];
        bs2 = ubp[2 * HD + jg] + wbp[2 * HD + jg];
        bs3 = ubp[3 * HD + jg] + wbp[3 * HD + jg];
    }
    float creg = 0.0f;   // cell state (column jg, batch=lane) on lanes 0-7

    // ---- stage x(0) into sX buffer 0 ----
    {
        const float4* x4 = (const float4*)x;
        float4* sX4 = (float4*)sX;
#pragma unroll
        for (int r = 0; r < 2; r++) {
            int i = tid + r * NT;
            sX4[i] = x4[((size_t)(i >> 6) * TT) * 64 + (i & 63)];
        }
    }
    __syncthreads();

    for (int p = 0; p <= TT; p++) {
        // keep x(p+1) L2-resident
        if (p + 1 < TT && tid < 64) {
            const float* pf = x + ((size_t)(tid >> 3) * TT + (p + 1)) * DI + (tid & 7) * 32;
            asm volatile("prefetch.global.L2 [%0];" :: "l"(pf));
        }

        // ---- phase 1: L0 warps do W0*x, pre-reduced to scalar r0 (acc dead
        //      across staging); warp 7 (idle L1 warp) polls period-p barrier ----
        float r0 = 0.0f;
        if (L0 && p < TT) {
            unsigned long long accx[32];
#pragma unroll
            for (int j = 0; j < 32; j++) accx[j] = 0ull;
            dotr<2, DI>(accx, wB, sX + (p & 1) * (BB * DI), lane);
            r0 = hreduce(accx, lane);
        }
        if (w == 7) poll_flags(lane, (unsigned)p);
        __syncthreads();

        // ---- phase 2: streamed staging (ld.cg -> STS, minimal live temps) ----
        {
            const float4* a4 = (const float4*)(g_hA + (p & 1) * (BB * HD));
            const float4* b4 = (const float4*)(g_hB + ((p + 1) & 1) * (BB * HD));
            float4* sA4 = (float4*)sA;
            float4* sB4 = (float4*)sB;
#pragma unroll
            for (int r = 0; r < 4; r++) {
                sA4[tid + r * NT] = __ldcg(a4 + tid + r * NT);
                sB4[tid + r * NT] = __ldcg(b4 + tid + r * NT);
            }
            if (p + 1 < TT) {
                const float4* x4 = (const float4*)x;
                float4* sX4 = (float4*)(sX + ((p + 1) & 1) * (BB * DI));
#pragma unroll
                for (int r = 0; r < 2; r++) {
                    int i = tid + r * NT;
                    sX4[i] = __ldcg(x4 + ((size_t)(i >> 6) * TT + (p + 1)) * 64 + (i & 63));
                }
            }
        }
        __syncthreads();

        // ---- phase 3: recurrent dots + cell update ----
        const bool active = L0 ? (p < TT) : (p > 0);
        if (active) {
            unsigned long long acc[32];
#pragma unroll
            for (int j = 0; j < 32; j++) acc[j] = 0ull;
            if (L0) {
                dotr<4, HD>(acc, wA, sA, lane);
            } else {
                dotr<4, HD>(acc, wA, sB, lane);
                dots<HD>(acc, sW1, sA, jl * 4, lane);
            }
            float v = hreduce(acc, lane) + r0;   // r0 = 0 on L1 warps

            const int bsel = lane & 7;
            float vi = __shfl_sync(0xffffffffu, v, bsel);
            float vf = __shfl_sync(0xffffffffu, v, bsel + 8);
            float vg = __shfl_sync(0xffffffffu, v, bsel + 16);
            float vo = __shfl_sync(0xffffffffu, v, bsel + 24);

            if (lane < 8) {   // lane = batch
                float iv = sigm(vi + bs0);
                float fv = sigm(vf + bs1);
                float gv = tanh_mufu(vg + bs2);
                float ov = sigm(vo + bs3);
                float c = fv * creg + iv * gv;
                creg = c;
                float h = ov * fmaxf(c, 0.0f);   // custom relu nonlinearity
                if (L0) {
                    __stcg(g_hA + ((p + 1) & 1) * (BB * HD) + lane * HD + jg, h);
                    if (p == TT - 1) { hh[lane * HD + jg] = h; cc[lane * HD + jg] = c; }
                } else {
                    const int t1 = p - 1;
                    __stcg(g_hB + (p & 1) * (BB * HD) + lane * HD + jg, h);
                    __stcg(h2seq + ((size_t)lane * TT + t1) * HD + jg, h);
                    if (t1 == TT - 1) {
                        hh[BB * HD + lane * HD + jg] = h;
                        cc[BB * HD + lane * HD + jg] = c;
                    }
                }
            }
        }

        // ---- publish completion of period p (single flag, R4 protocol) ----
        __syncthreads();
        if (tid == 0) {
            unsigned v = (unsigned)(p + 1);
            asm volatile("st.release.gpu.global.b32 [%0], %1;"
                         :: "l"(g_flags + bid), "r"(v) : "memory");
        }
    }
}

// ---------------- host launch ----------------
extern "C" void kernel_launch(void* const* d_in, const int* in_sizes, int n_in,
                              void* d_out, int out_size) {
    (void)in_sizes; (void)n_in; (void)out_size;
    const float* x   = (const float*)d_in[0];
    const float* w0w = (const float*)d_in[1];
    const float* w0b = (const float*)d_in[2];
    const float* u0w = (const float*)d_in[3];
    const float* u0b = (const float*)d_in[4];
    const float* w1w = (const float*)d_in[5];
    const float* w1b = (const float*)d_in[6];
    const float* u1w = (const float*)d_in[7];
    const float* u1b = (const float*)d_in[8];
    float* out = (float*)d_out;

    const size_t H2 = (size_t)BB * TT * HD;
    float* hh = out + H2;                     // [2, B, H]
    float* cc = hh + 2 * BB * HD;             // [2, B, H]

    const size_t smem = (size_t)(16 * HD + 2 * BB * HD + 2 * BB * DI)
                        * sizeof(float);      // 80 KB
    cudaFuncSetAttribute(lstm_fused_kernel, cudaFuncAttributeMaxDynamicSharedMemorySize,
                         (int)smem);

    init_kernel<<<32, 256>>>();
    lstm_fused_kernel<<<NB, NT, smem>>>(x, u0w, w0w, u0b, w0b,
                                        u1w, w1w, u1b, w1b,
                                        out, hh, cc);
}